// round 8
// baseline (speedup 1.0000x reference)
#include <cuda_runtime.h>
#include <math.h>

#define BB 256
#define SS 365
#define FD 32
#define FS 27
#define HH 256
#define G3 768

#define OUT_OFF   0
#define HN_OFF    93440
#define CN_OFF    24014080

#define NCOL 24            // cols per CTA: 3 gates x 8 i
#define WSTRIDE_W 288      // w row stride; quarter q at offset q*72 (banks 0/8/16/24)
#define WSTRIDE_H 260      // h row stride (8 distinct bank-quads across bg)
#define HSM_OFF (NCOL * WSTRIDE_W)   // 6912 floats

typedef unsigned long long u64;

__device__ float g_xproj[(size_t)SS * G3 * BB];   // [s][col][b]
__device__ float g_h[2][BB * HH];                 // double-buffered hidden state
__device__ int   g_flag[8 * 32];                  // group bt at bt*32 (one 128B line), 32 used

__device__ __forceinline__ u64 ffma2(u64 a, u64 b, u64 c) {
    u64 d;
    asm("fma.rn.f32x2 %0, %1, %2, %3;" : "=l"(d) : "l"(a), "l"(b), "l"(c));
    return d;
}
__device__ __forceinline__ u64 dup2(float x) {
    u64 r;
    asm("mov.b64 %0, {%1, %1};" : "=l"(r) : "f"(x));
    return r;
}
__device__ __forceinline__ float sigm_f(float x) {
    return __fdividef(1.0f, 1.0f + __expf(-x));
}
__device__ __forceinline__ float tanh_f(float x) {
    float t = __expf(2.0f * x);
    return 1.0f - __fdividef(2.0f, t + 1.0f);
}

__global__ void reset_kernel() {
    int idx = blockIdx.x * blockDim.x + threadIdx.x;
    if (idx < 8 * 32) g_flag[idx] = 0;
}

__global__ void dummy_kernel() {}   // aligns ncu -s 5 -c 1 capture onto ealstm_kernel

// x_proj precompute with packed f32x2. grid: S blocks, 256 threads (thread = b).
__global__ void __launch_bounds__(256) xproj_kernel(const float* __restrict__ x_d,
                                                    const float* __restrict__ W_ih) {
    extern __shared__ float smf[];  // [pair][d*2+half], 384*64 floats
    const int s = blockIdx.x;
    const int tid = threadIdx.x;

    for (int idx = tid; idx < FD * G3; idx += 256) {
        int d = idx / G3, col = idx % G3;
        smf[(col >> 1) * 64 + d * 2 + (col & 1)] = W_ih[idx];
    }
    __syncthreads();

    u64 xp[FD];
    {
        const float4* xp4 = reinterpret_cast<const float4*>(x_d + ((size_t)tid * SS + s) * FD);
#pragma unroll
        for (int m = 0; m < 8; m++) {
            float4 v = xp4[m];
            xp[4*m]   = dup2(v.x);
            xp[4*m+1] = dup2(v.y);
            xp[4*m+2] = dup2(v.z);
            xp[4*m+3] = dup2(v.w);
        }
    }

    float* dst = g_xproj + (size_t)s * G3 * BB + tid;
    for (int p = 0; p < G3 / 2; p++) {
        u64 acc = 0ull;
        const ulonglong2* wp = reinterpret_cast<const ulonglong2*>(&smf[p * 64]);
#pragma unroll
        for (int dd = 0; dd < 16; dd++) {
            ulonglong2 q = wp[dd];
            acc = ffma2(xp[2*dd],     q.x, acc);
            acc = ffma2(xp[2*dd + 1], q.y, acc);
        }
        float2 pr = *reinterpret_cast<float2*>(&acc);
        dst[(size_t)(2*p)     * BB] = pr.x;
        dst[(size_t)(2*p + 1) * BB] = pr.y;
    }
}

// Persistent recurrence: grid 256 = 8 batch groups (32 b) x 32 CTAs (24 cols), 2 CTAs/SM.
// 128 threads: warp w in [0,4) -> i pair {ic*8 + 2w, +1}; lane: ks=lane>>3, bg=lane&7.
__global__ void __launch_bounds__(128, 2) ealstm_kernel(const float* __restrict__ x_s,
                                                        const float* __restrict__ W_hh,
                                                        const float* __restrict__ W_sh,
                                                        const float* __restrict__ bias,
                                                        const float* __restrict__ bias_s,
                                                        float* __restrict__ d_out) {
    extern __shared__ float smem[];
    float* w_sm = smem;             // [24][288], quarter q of k at col offset q*72
    float* h_sm = smem + HSM_OFF;   // [32][260]

    const int tid  = threadIdx.x;
    const int warp = tid >> 5;
    const int lane = tid & 31;
    const int ks   = lane >> 3;
    const int bg   = lane & 7;
    const int bt   = blockIdx.x >> 5;   // batch group
    const int ic   = blockIdx.x & 31;   // i-chunk of 8

    // ---- load W_hh slice: w_sm[c][k_phys], c = gate*8 + il, k_phys = k + (k>>6)*8 ----
    for (int idx = tid; idx < NCOL * HH; idx += 128) {
        int c = idx % NCOL, k = idx / NCOL;
        int gate = c >> 3, il = c & 7;
        int kp = k + ((k >> 6) << 3);
        w_sm[c * WSTRIDE_W + kp] = W_hh[k * G3 + gate * HH + ic * 8 + il];
    }

    const int b_glob = bt * 32 + bg + 8 * ks;
    const int i0     = ic * 8 + warp * 2;

    float bf[2], bo[2], bgc[2], ig[2], creg[2];
#pragma unroll
    for (int il = 0; il < 2; il++) {
        int i = i0 + il;
        bf[il]  = bias[i];
        bo[il]  = bias[HH + i];
        bgc[il] = bias[2 * HH + i];
        float sum = bias_s[i];
        for (int d = 0; d < FS; d++)
            sum = fmaf(x_s[b_glob * FS + d], W_sh[d * HH + i], sum);
        ig[il] = 1.0f / (1.0f + expf(-sum));
        creg[il] = 0.0f;
    }
    __syncthreads();

    int hrow[4], wrow[6];
#pragma unroll
    for (int j = 0; j < 4; j++) hrow[j] = (bg + 8 * j) * WSTRIDE_H + ks * 64;
#pragma unroll
    for (int g = 0; g < 3; g++)
#pragma unroll
        for (int il = 0; il < 2; il++)
            wrow[g * 2 + il] = (g * 8 + warp * 2 + il) * WSTRIDE_W + ks * 72;

    // h tile fill: f = m*128 + tid, m in [0,16); row = 2m + tid>>6, k = (tid&63)*4
    const int hl_row = tid >> 6;          // 0..1
    const int hl_k   = (tid & 63) * 4;

    int* my_flag = &g_flag[bt * 32 + ic];

    for (int s = 0; s < SS; s++) {
        // ---- prefetch x_proj additive terms (independent of sync) ----
        float xf[2], xo[2], xg[2];
        {
            const size_t xrow = (size_t)s * G3 * BB + b_glob;
#pragma unroll
            for (int il = 0; il < 2; il++) {
                int i = i0 + il;
                xf[il] = __ldcg(&g_xproj[xrow + (size_t)i * BB]);
                xo[il] = __ldcg(&g_xproj[xrow + (size_t)(HH + i) * BB]);
                xg[il] = __ldcg(&g_xproj[xrow + (size_t)(2 * HH + i) * BB]);
            }
        }

        if (s == 0) {
#pragma unroll
            for (int m = 0; m < 16; m++) {
                int rl = 2 * m + hl_row;
                *reinterpret_cast<float4*>(&h_sm[rl * WSTRIDE_H + hl_k]) =
                    make_float4(0.f, 0.f, 0.f, 0.f);
            }
            __syncthreads();
        } else {
            // ---- wait: all 32 producer flags of this group >= s (one 128B line) ----
            if (warp == 0) {
                const int* fp = &g_flag[bt * 32 + lane];
                int v;
                do {
                    asm volatile("ld.acquire.gpu.global.b32 %0, [%1];"
                                 : "=r"(v) : "l"(fp) : "memory");
                } while (v < s);
            }
            __syncthreads();

            // ---- load h tile [32 x 256] from contiguous g_h double buffer ----
            {
                const float* src_base = g_h[s & 1] + (size_t)bt * 32 * HH;
#pragma unroll
                for (int m = 0; m < 16; m++) {
                    int rl = 2 * m + hl_row;
                    float4 v = __ldcg(reinterpret_cast<const float4*>(src_base + rl * HH + hl_k));
                    *reinterpret_cast<float4*>(&h_sm[rl * WSTRIDE_H + hl_k]) = v;
                }
            }
            __syncthreads();
        }

        // ---- packed f32x2 accumulation over this lane's k quarter ----
        u64 acc[4][6];
#pragma unroll
        for (int j = 0; j < 4; j++)
#pragma unroll
            for (int c = 0; c < 6; c++) acc[j][c] = 0ull;

#pragma unroll 4
        for (int kk = 0; kk < 16; kk++) {
            const int o = kk * 4;
            ulonglong2 h2[4];
#pragma unroll
            for (int j = 0; j < 4; j++)
                h2[j] = *reinterpret_cast<const ulonglong2*>(&h_sm[hrow[j] + o]);
#pragma unroll
            for (int c = 0; c < 6; c++) {
                ulonglong2 w2 = *reinterpret_cast<const ulonglong2*>(&w_sm[wrow[c] + o]);
#pragma unroll
                for (int j = 0; j < 4; j++) {
                    acc[j][c] = ffma2(h2[j].x, w2.x, acc[j][c]);
                    acc[j][c] = ffma2(h2[j].y, w2.y, acc[j][c]);
                }
            }
        }

        // ---- horizontal add + reduce over k quarters ----
        float accs[4][6];
#pragma unroll
        for (int j = 0; j < 4; j++)
#pragma unroll
            for (int c = 0; c < 6; c++) {
                float2 p = *reinterpret_cast<float2*>(&acc[j][c]);
                float v = p.x + p.y;
                v += __shfl_xor_sync(0xffffffffu, v, 8);
                v += __shfl_xor_sync(0xffffffffu, v, 16);
                accs[j][c] = v;
            }

        float g6[6];
#pragma unroll
        for (int c = 0; c < 6; c++) {
            float v0 = (ks & 1) ? accs[1][c] : accs[0][c];
            float v2 = (ks & 1) ? accs[3][c] : accs[2][c];
            g6[c] = (ks & 2) ? v2 : v0;
        }

        // ---- gate epilogue ----
        float hv[2], cv[2];
#pragma unroll
        for (int il = 0; il < 2; il++) {
            float f = g6[il]     + bf[il]  + xf[il];
            float o = g6[2 + il] + bo[il]  + xo[il];
            float g = g6[4 + il] + bgc[il] + xg[il];
            float cn = sigm_f(f) * creg[il] + ig[il] * tanh_f(g);
            float hn = sigm_f(o) * tanh_f(cn);
            creg[il] = cn;
            hv[il] = hn; cv[il] = cn;
        }

        // ---- publish h' to exchange buffer, release flag, then cold outputs ----
        float2 h2v = make_float2(hv[0], hv[1]);
        float2 c2v = make_float2(cv[0], cv[1]);
        __stcg(reinterpret_cast<float2*>(&g_h[(s + 1) & 1][b_glob * HH + i0]), h2v);

        __syncthreads();   // all warps' h' stores issued before the flag release
        if (tid == 0) {
            asm volatile("st.release.gpu.global.b32 [%0], %1;"
                         :: "l"(my_flag), "r"(s + 1) : "memory");
        }

        size_t obase = ((size_t)b_glob * SS + s) * HH + i0;
        *reinterpret_cast<float2*>(&d_out[HN_OFF + obase]) = h2v;
        *reinterpret_cast<float2*>(&d_out[CN_OFF + obase]) = c2v;
    }
}

__global__ void __launch_bounds__(256) fc_kernel(const float* __restrict__ W_fc,
                                                 const float* __restrict__ b_fc,
                                                 float* __restrict__ d_out) {
    int gidx = blockIdx.x * 8 + (threadIdx.x >> 5);
    if (gidx >= BB * SS) return;
    int lane = threadIdx.x & 31;

    const float4* h4 = reinterpret_cast<const float4*>(d_out + HN_OFF + (size_t)gidx * HH) + lane * 2;
    const float4* w4 = reinterpret_cast<const float4*>(W_fc) + lane * 2;
    float4 a = h4[0], b = h4[1];
    float4 wa = w4[0], wb = w4[1];
    float sum = a.x * wa.x + a.y * wa.y + a.z * wa.z + a.w * wa.w
              + b.x * wb.x + b.y * wb.y + b.z * wb.z + b.w * wb.w;
#pragma unroll
    for (int off = 16; off > 0; off >>= 1)
        sum += __shfl_xor_sync(0xffffffffu, sum, off);
    if (lane == 0) d_out[OUT_OFF + gidx] = sum + b_fc[0];
}

extern "C" void kernel_launch(void* const* d_in, const int* in_sizes, int n_in,
                              void* d_out, int out_size) {
    const float* x_d    = (const float*)d_in[0];
    const float* x_s    = (const float*)d_in[1];
    const float* W_ih   = (const float*)d_in[2];
    const float* W_hh   = (const float*)d_in[3];
    const float* W_sh   = (const float*)d_in[4];
    const float* bias   = (const float*)d_in[5];
    const float* bias_s = (const float*)d_in[6];
    const float* W_fc   = (const float*)d_in[7];
    const float* b_fc   = (const float*)d_in[8];
    float* out = (float*)d_out;

    const int SMEM_X    = (G3 / 2) * 64 * sizeof(float);                            // 98304
    const int SMEM_MAIN = (NCOL * WSTRIDE_W + 32 * WSTRIDE_H) * sizeof(float);      // 60928

    cudaFuncSetAttribute(xproj_kernel, cudaFuncAttributeMaxDynamicSharedMemorySize, SMEM_X);
    cudaFuncSetAttribute(ealstm_kernel, cudaFuncAttributeMaxDynamicSharedMemorySize, SMEM_MAIN);

    reset_kernel<<<1, 256>>>();
    xproj_kernel<<<SS, 256, SMEM_X>>>(x_d, W_ih);
    dummy_kernel<<<1, 32>>>();   // launch alignment: puts ealstm on ncu's captured slot
    ealstm_kernel<<<256, 128, SMEM_MAIN>>>(x_s, W_hh, W_sh, bias, bias_s, out);
    fc_kernel<<<(BB * SS + 7) / 8, 256>>>(W_fc, b_fc, out);
}

// round 9
// speedup vs baseline: 1.2627x; 1.2627x over previous
#include <cuda_runtime.h>
#include <math.h>

#define BB 256
#define SS 365
#define FD 32
#define FS 27
#define HH 256
#define G3 768

#define OUT_OFF   0
#define HN_OFF    93440
#define CN_OFF    24014080

#define WSTRIDE_W 288              // w rows; quarter q at q*72 -> banks {0,8,16,24}
#define WSTRIDE_H 260              // h rows; 4-phase floor (unchanged from R3)
#define HSM_OFF (48 * WSTRIDE_W)   // 13824 floats

typedef unsigned long long u64;

__device__ float g_xproj[(size_t)SS * G3 * BB];   // [s][col][b]
__device__ float g_h[2][BB * HH];                 // double-buffered hidden state
__device__ int   g_cnt[8];                        // per-batch-tile step counters

__device__ __forceinline__ u64 ffma2(u64 a, u64 b, u64 c) {
    u64 d;
    asm("fma.rn.f32x2 %0, %1, %2, %3;" : "=l"(d) : "l"(a), "l"(b), "l"(c));
    return d;
}
__device__ __forceinline__ u64 dup2(float x) {
    u64 r;
    asm("mov.b64 %0, {%1, %1};" : "=l"(r) : "f"(x));
    return r;
}
__device__ __forceinline__ float sigm_f(float x) {
    return __fdividef(1.0f, 1.0f + __expf(-x));
}
__device__ __forceinline__ float tanh_f(float x) {
    float t = __expf(2.0f * x);
    return 1.0f - __fdividef(2.0f, t + 1.0f);
}

__global__ void reset_kernel() {
    int idx = blockIdx.x * blockDim.x + threadIdx.x;
    if (idx < BB * HH) g_h[0][idx] = 0.0f;
    if (idx < 8) g_cnt[idx] = 0;
}

__global__ void dummy_kernel() {}   // aligns ncu -s 5 -c 1 capture onto ealstm_kernel

// x_proj precompute with packed f32x2. grid: S blocks, 256 threads (thread = b).
__global__ void __launch_bounds__(256) xproj_kernel(const float* __restrict__ x_d,
                                                    const float* __restrict__ W_ih) {
    extern __shared__ float smf[];  // [pair][d*2+half], 384*64 floats
    const int s = blockIdx.x;
    const int tid = threadIdx.x;

    for (int idx = tid; idx < FD * G3; idx += 256) {
        int d = idx / G3, col = idx % G3;
        smf[(col >> 1) * 64 + d * 2 + (col & 1)] = W_ih[idx];
    }
    __syncthreads();

    u64 xp[FD];
    {
        const float4* xp4 = reinterpret_cast<const float4*>(x_d + ((size_t)tid * SS + s) * FD);
#pragma unroll
        for (int m = 0; m < 8; m++) {
            float4 v = xp4[m];
            xp[4*m]   = dup2(v.x);
            xp[4*m+1] = dup2(v.y);
            xp[4*m+2] = dup2(v.z);
            xp[4*m+3] = dup2(v.w);
        }
    }

    float* dst = g_xproj + (size_t)s * G3 * BB + tid;
    for (int p = 0; p < G3 / 2; p++) {
        u64 acc = 0ull;
        const ulonglong2* wp = reinterpret_cast<const ulonglong2*>(&smf[p * 64]);
#pragma unroll
        for (int dd = 0; dd < 16; dd++) {
            ulonglong2 q = wp[dd];
            acc = ffma2(xp[2*dd],     q.x, acc);
            acc = ffma2(xp[2*dd + 1], q.y, acc);
        }
        float2 pr = *reinterpret_cast<float2*>(&acc);
        dst[(size_t)(2*p)     * BB] = pr.x;
        dst[(size_t)(2*p + 1) * BB] = pr.y;
    }
}

// Persistent recurrence: grid 128 = 8 batch tiles (32 b) x 16 CTAs (48 cols). 256 threads.
// warp w -> i pair {ic*16+2w, +1}; lane: ks=lane>>3 (k quarter), bg=lane&7.
__global__ void __launch_bounds__(256, 1) ealstm_kernel(const float* __restrict__ x_s,
                                                        const float* __restrict__ W_hh,
                                                        const float* __restrict__ W_sh,
                                                        const float* __restrict__ bias,
                                                        const float* __restrict__ bias_s,
                                                        float* __restrict__ d_out) {
    extern __shared__ float smem[];
    float* w_sm = smem;             // [48][288], k-gap swizzled
    float* h_sm = smem + HSM_OFF;   // [32][260], plain

    const int tid  = threadIdx.x;
    const int warp = tid >> 5;
    const int lane = tid & 31;
    const int ks   = lane >> 3;
    const int bg   = lane & 7;
    const int bt   = blockIdx.x >> 4;
    const int ic   = blockIdx.x & 15;

    // ---- load W_hh slice: w_sm[c][k_phys], k_phys = k + (k>>6)*8 ----
    for (int idx = tid; idx < 48 * 256; idx += 256) {
        int c = idx % 48, k = idx / 48;
        int gate = c >> 4, il = c & 15;
        int kp = k + ((k >> 6) << 3);
        w_sm[c * WSTRIDE_W + kp] = W_hh[k * G3 + gate * HH + ic * 16 + il];
    }

    const int b_glob = bt * 32 + bg + 8 * ks;
    const int i0     = ic * 16 + warp * 2;

    float bf[2], bo[2], bgc[2], ig[2], creg[2];
#pragma unroll
    for (int il = 0; il < 2; il++) {
        int i = i0 + il;
        bf[il]  = bias[i];
        bo[il]  = bias[HH + i];
        bgc[il] = bias[2 * HH + i];
        float sum = bias_s[i];
        for (int d = 0; d < FS; d++)
            sum = fmaf(x_s[b_glob * FS + d], W_sh[d * HH + i], sum);
        ig[il] = 1.0f / (1.0f + expf(-sum));
        creg[il] = 0.0f;
    }
    __syncthreads();

    int hrow[4], wrow[6];
#pragma unroll
    for (int j = 0; j < 4; j++) hrow[j] = (bg + 8 * j) * WSTRIDE_H + ks * 64;
#pragma unroll
    for (int g = 0; g < 3; g++)
#pragma unroll
        for (int il = 0; il < 2; il++)
            wrow[g * 2 + il] = (g * 16 + warp * 2 + il) * WSTRIDE_W + ks * 72;

    // h tile fill: f = m*256 + tid, m in [0,8); row = 4m + tid>>6, k = (tid&63)*4
    const int hl_row = tid >> 6;          // 0..3
    const int hl_k   = (tid & 63) * 4;

    for (int s = 0; s < SS; s++) {
        // ---- wait for h input of step s ----
        if (tid == 0) {
            volatile int* p = &g_cnt[bt];
            int target = 16 * s;
            while (*p < target) { }
        }
        __syncthreads();

        // ---- load h tile [32 x 256] from global double buffer (coalesced, L2-only) ----
        {
            const float* src_base = g_h[s & 1] + (size_t)bt * 32 * HH;
#pragma unroll
            for (int m = 0; m < 8; m++) {
                int rl = 4 * m + hl_row;
                float4 v = __ldcg(reinterpret_cast<const float4*>(src_base + rl * HH + hl_k));
                *reinterpret_cast<float4*>(&h_sm[rl * WSTRIDE_H + hl_k]) = v;
            }
        }

        // ---- prefetch x_proj additive terms ----
        float xf[2], xo[2], xg[2];
        {
            const size_t xrow = (size_t)s * G3 * BB + b_glob;
#pragma unroll
            for (int il = 0; il < 2; il++) {
                int i = i0 + il;
                xf[il] = __ldg(&g_xproj[xrow + (size_t)i * BB]);
                xo[il] = __ldg(&g_xproj[xrow + (size_t)(HH + i) * BB]);
                xg[il] = __ldg(&g_xproj[xrow + (size_t)(2 * HH + i) * BB]);
            }
        }
        __syncthreads();

        // ---- packed f32x2 accumulation over this lane's k quarter ----
        u64 acc[4][6];
#pragma unroll
        for (int j = 0; j < 4; j++)
#pragma unroll
            for (int c = 0; c < 6; c++) acc[j][c] = 0ull;

#pragma unroll 4
        for (int kk = 0; kk < 16; kk++) {
            const int o = kk * 4;
            ulonglong2 h2[4];
#pragma unroll
            for (int j = 0; j < 4; j++)
                h2[j] = *reinterpret_cast<const ulonglong2*>(&h_sm[hrow[j] + o]);
#pragma unroll
            for (int c = 0; c < 6; c++) {
                ulonglong2 w2 = *reinterpret_cast<const ulonglong2*>(&w_sm[wrow[c] + o]);
#pragma unroll
                for (int j = 0; j < 4; j++) {
                    acc[j][c] = ffma2(h2[j].x, w2.x, acc[j][c]);
                    acc[j][c] = ffma2(h2[j].y, w2.y, acc[j][c]);
                }
            }
        }

        // ---- horizontal add + reduce over k quarters ----
        float accs[4][6];
#pragma unroll
        for (int j = 0; j < 4; j++)
#pragma unroll
            for (int c = 0; c < 6; c++) {
                float2 p = *reinterpret_cast<float2*>(&acc[j][c]);
                float v = p.x + p.y;
                v += __shfl_xor_sync(0xffffffffu, v, 8);
                v += __shfl_xor_sync(0xffffffffu, v, 16);
                accs[j][c] = v;
            }

        float g6[6];
#pragma unroll
        for (int c = 0; c < 6; c++) {
            float v0 = (ks & 1) ? accs[1][c] : accs[0][c];
            float v2 = (ks & 1) ? accs[3][c] : accs[2][c];
            g6[c] = (ks & 2) ? v2 : v0;
        }

        // ---- gate epilogue ----
        float hv[2], cv[2];
#pragma unroll
        for (int il = 0; il < 2; il++) {
            float f = g6[il]     + bf[il]  + xf[il];
            float o = g6[2 + il] + bo[il]  + xo[il];
            float g = g6[4 + il] + bgc[il] + xg[il];
            float cn = sigm_f(f) * creg[il] + ig[il] * tanh_f(g);
            float hn = sigm_f(o) * tanh_f(cn);
            creg[il] = cn;
            hv[il] = hn; cv[il] = cn;
        }

        // ---- publish h1 + outputs, then release (R3 ordering) ----
        {
            float2 h2v = make_float2(hv[0], hv[1]);
            float2 c2v = make_float2(cv[0], cv[1]);
            __stcg(reinterpret_cast<float2*>(&g_h[(s + 1) & 1][b_glob * HH + i0]), h2v);
            size_t obase = ((size_t)b_glob * SS + s) * HH + i0;
            *reinterpret_cast<float2*>(&d_out[HN_OFF + obase]) = h2v;
            *reinterpret_cast<float2*>(&d_out[CN_OFF + obase]) = c2v;
        }

        __threadfence();
        __syncthreads();
        if (tid == 0) atomicAdd(&g_cnt[bt], 1);
    }
}

__global__ void __launch_bounds__(256) fc_kernel(const float* __restrict__ W_fc,
                                                 const float* __restrict__ b_fc,
                                                 float* __restrict__ d_out) {
    int gidx = blockIdx.x * 8 + (threadIdx.x >> 5);
    if (gidx >= BB * SS) return;
    int lane = threadIdx.x & 31;

    const float4* h4 = reinterpret_cast<const float4*>(d_out + HN_OFF + (size_t)gidx * HH) + lane * 2;
    const float4* w4 = reinterpret_cast<const float4*>(W_fc) + lane * 2;
    float4 a = h4[0], b = h4[1];
    float4 wa = w4[0], wb = w4[1];
    float sum = a.x * wa.x + a.y * wa.y + a.z * wa.z + a.w * wa.w
              + b.x * wb.x + b.y * wb.y + b.z * wb.z + b.w * wb.w;
#pragma unroll
    for (int off = 16; off > 0; off >>= 1)
        sum += __shfl_xor_sync(0xffffffffu, sum, off);
    if (lane == 0) d_out[OUT_OFF + gidx] = sum + b_fc[0];
}

extern "C" void kernel_launch(void* const* d_in, const int* in_sizes, int n_in,
                              void* d_out, int out_size) {
    const float* x_d    = (const float*)d_in[0];
    const float* x_s    = (const float*)d_in[1];
    const float* W_ih   = (const float*)d_in[2];
    const float* W_hh   = (const float*)d_in[3];
    const float* W_sh   = (const float*)d_in[4];
    const float* bias   = (const float*)d_in[5];
    const float* bias_s = (const float*)d_in[6];
    const float* W_fc   = (const float*)d_in[7];
    const float* b_fc   = (const float*)d_in[8];
    float* out = (float*)d_out;

    const int SMEM_X    = (G3 / 2) * 64 * sizeof(float);                          // 98304
    const int SMEM_MAIN = (48 * WSTRIDE_W + 32 * WSTRIDE_H) * sizeof(float);      // 88576

    cudaFuncSetAttribute(xproj_kernel, cudaFuncAttributeMaxDynamicSharedMemorySize, SMEM_X);
    cudaFuncSetAttribute(ealstm_kernel, cudaFuncAttributeMaxDynamicSharedMemorySize, SMEM_MAIN);

    reset_kernel<<<256, 256>>>();
    xproj_kernel<<<SS, 256, SMEM_X>>>(x_d, W_ih);
    dummy_kernel<<<1, 32>>>();   // keeps ncu's captured launch on ealstm_kernel
    ealstm_kernel<<<128, 256, SMEM_MAIN>>>(x_s, W_hh, W_sh, bias, bias_s, out);
    fc_kernel<<<(BB * SS + 7) / 8, 256>>>(W_fc, b_fc, out);
}

// round 10
// speedup vs baseline: 1.3163x; 1.0425x over previous
#include <cuda_runtime.h>
#include <math.h>

#define BB 256
#define SS 365
#define FD 32
#define FS 27
#define HH 256
#define G3 768

#define OUT_OFF   0
#define HN_OFF    93440
#define CN_OFF    24014080

#define WSTRIDE_W 288              // w rows; quarter q at q*72 -> banks {0,8,16,24}
#define WSTRIDE_H 260              // h rows; 4-phase floor
#define HSM_OFF (48 * WSTRIDE_W)

typedef unsigned long long u64;

__device__ float g_xproj[(size_t)SS * G3 * BB];   // [s][col][b]
__device__ float g_h[2][BB * HH];                 // double-buffered hidden state
__device__ int   g_flag[128 * 32];                // flag (bt*16+ic) at its own 128B line

__device__ __forceinline__ u64 ffma2(u64 a, u64 b, u64 c) {
    u64 d;
    asm("fma.rn.f32x2 %0, %1, %2, %3;" : "=l"(d) : "l"(a), "l"(b), "l"(c));
    return d;
}
__device__ __forceinline__ u64 dup2(float x) {
    u64 r;
    asm("mov.b64 %0, {%1, %1};" : "=l"(r) : "f"(x));
    return r;
}
__device__ __forceinline__ float sigm_f(float x) {
    return __fdividef(1.0f, 1.0f + __expf(-x));
}
__device__ __forceinline__ float tanh_f(float x) {
    float t = __expf(2.0f * x);
    return 1.0f - __fdividef(2.0f, t + 1.0f);
}

__global__ void reset_kernel() {
    int idx = blockIdx.x * blockDim.x + threadIdx.x;
    if (idx < BB * HH) g_h[0][idx] = 0.0f;
    if (idx < 128 * 32) g_flag[idx] = 0;
}

__global__ void dummy_kernel() {}   // keeps ncu's captured launch on ealstm_kernel

// x_proj precompute with packed f32x2. grid: S blocks, 256 threads (thread = b).
__global__ void __launch_bounds__(256) xproj_kernel(const float* __restrict__ x_d,
                                                    const float* __restrict__ W_ih) {
    extern __shared__ float smf[];  // [pair][d*2+half], 384*64 floats
    const int s = blockIdx.x;
    const int tid = threadIdx.x;

    for (int idx = tid; idx < FD * G3; idx += 256) {
        int d = idx / G3, col = idx % G3;
        smf[(col >> 1) * 64 + d * 2 + (col & 1)] = W_ih[idx];
    }
    __syncthreads();

    u64 xp[FD];
    {
        const float4* xp4 = reinterpret_cast<const float4*>(x_d + ((size_t)tid * SS + s) * FD);
#pragma unroll
        for (int m = 0; m < 8; m++) {
            float4 v = xp4[m];
            xp[4*m]   = dup2(v.x);
            xp[4*m+1] = dup2(v.y);
            xp[4*m+2] = dup2(v.z);
            xp[4*m+3] = dup2(v.w);
        }
    }

    float* dst = g_xproj + (size_t)s * G3 * BB + tid;
    for (int p = 0; p < G3 / 2; p++) {
        u64 acc = 0ull;
        const ulonglong2* wp = reinterpret_cast<const ulonglong2*>(&smf[p * 64]);
#pragma unroll
        for (int dd = 0; dd < 16; dd++) {
            ulonglong2 q = wp[dd];
            acc = ffma2(xp[2*dd],     q.x, acc);
            acc = ffma2(xp[2*dd + 1], q.y, acc);
        }
        float2 pr = *reinterpret_cast<float2*>(&acc);
        dst[(size_t)(2*p)     * BB] = pr.x;
        dst[(size_t)(2*p + 1) * BB] = pr.y;
    }
}

// Persistent recurrence: grid 128 = 8 batch tiles (32 b) x 16 CTAs (48 cols). 256 threads.
__global__ void __launch_bounds__(256, 1) ealstm_kernel(const float* __restrict__ x_s,
                                                        const float* __restrict__ W_hh,
                                                        const float* __restrict__ W_sh,
                                                        const float* __restrict__ bias,
                                                        const float* __restrict__ bias_s,
                                                        float* __restrict__ d_out) {
    extern __shared__ float smem[];
    float* w_sm = smem;             // [48][288], k-gap swizzled
    float* h_sm = smem + HSM_OFF;   // [32][260]

    const int tid  = threadIdx.x;
    const int warp = tid >> 5;
    const int lane = tid & 31;
    const int ks   = lane >> 3;
    const int bg   = lane & 7;
    const int bt   = blockIdx.x >> 4;
    const int ic   = blockIdx.x & 15;

    for (int idx = tid; idx < 48 * 256; idx += 256) {
        int c = idx % 48, k = idx / 48;
        int gate = c >> 4, il = c & 15;
        int kp = k + ((k >> 6) << 3);
        w_sm[c * WSTRIDE_W + kp] = W_hh[k * G3 + gate * HH + ic * 16 + il];
    }

    const int b_glob = bt * 32 + bg + 8 * ks;
    const int i0     = ic * 16 + warp * 2;

    float bf[2], bo[2], bgc[2], ig[2], creg[2];
#pragma unroll
    for (int il = 0; il < 2; il++) {
        int i = i0 + il;
        bf[il]  = bias[i];
        bo[il]  = bias[HH + i];
        bgc[il] = bias[2 * HH + i];
        float sum = bias_s[i];
        for (int d = 0; d < FS; d++)
            sum = fmaf(x_s[b_glob * FS + d], W_sh[d * HH + i], sum);
        ig[il] = 1.0f / (1.0f + expf(-sum));
        creg[il] = 0.0f;
    }
    __syncthreads();

    int hrow[4], wrow[6];
#pragma unroll
    for (int j = 0; j < 4; j++) hrow[j] = (bg + 8 * j) * WSTRIDE_H + ks * 64;
#pragma unroll
    for (int g = 0; g < 3; g++)
#pragma unroll
        for (int il = 0; il < 2; il++)
            wrow[g * 2 + il] = (g * 16 + warp * 2 + il) * WSTRIDE_W + ks * 72;

    // h tile fill: f = m*256 + tid, m in [0,8); row = 4m + tid>>6, k = (tid&63)*4
    const int hl_row = tid >> 6;
    const int hl_k   = (tid & 63) * 4;

    int* my_flag = &g_flag[(bt * 16 + ic) * 32];
    const int* grp_flags = &g_flag[bt * 16 * 32];

    for (int s = 0; s < SS; s++) {
        // ---- wait: every warp polls all 16 producer flags (parallel lanes) ----
        if (s > 0) {
            const int* fp = grp_flags + (lane & 15) * 32;
            for (;;) {
                int v;
                asm volatile("ld.acquire.gpu.global.b32 %0, [%1];"
                             : "=r"(v) : "l"(fp) : "memory");
                if (__all_sync(0xffffffffu, v >= s)) break;
            }
        }

        // ---- load h tile [32 x 256] (warp-local: can start right after its own poll) ----
        {
            const float* src_base = g_h[s & 1] + (size_t)bt * 32 * HH;
#pragma unroll
            for (int m = 0; m < 8; m++) {
                int rl = 4 * m + hl_row;
                float4 v = __ldcg(reinterpret_cast<const float4*>(src_base + rl * HH + hl_k));
                *reinterpret_cast<float4*>(&h_sm[rl * WSTRIDE_H + hl_k]) = v;
            }
        }

        // ---- prefetch x_proj additive terms (consumed in epilogue) ----
        float xf[2], xo[2], xg[2];
        {
            const size_t xrow = (size_t)s * G3 * BB + b_glob;
#pragma unroll
            for (int il = 0; il < 2; il++) {
                int i = i0 + il;
                xf[il] = __ldg(&g_xproj[xrow + (size_t)i * BB]);
                xo[il] = __ldg(&g_xproj[xrow + (size_t)(HH + i) * BB]);
                xg[il] = __ldg(&g_xproj[xrow + (size_t)(2 * HH + i) * BB]);
            }
        }
        __syncthreads();

        // ---- packed f32x2 accumulation over this lane's k quarter ----
        u64 acc[4][6];
#pragma unroll
        for (int j = 0; j < 4; j++)
#pragma unroll
            for (int c = 0; c < 6; c++) acc[j][c] = 0ull;

#pragma unroll 4
        for (int kk = 0; kk < 16; kk++) {
            const int o = kk * 4;
            ulonglong2 h2[4];
#pragma unroll
            for (int j = 0; j < 4; j++)
                h2[j] = *reinterpret_cast<const ulonglong2*>(&h_sm[hrow[j] + o]);
#pragma unroll
            for (int c = 0; c < 6; c++) {
                ulonglong2 w2 = *reinterpret_cast<const ulonglong2*>(&w_sm[wrow[c] + o]);
#pragma unroll
                for (int j = 0; j < 4; j++) {
                    acc[j][c] = ffma2(h2[j].x, w2.x, acc[j][c]);
                    acc[j][c] = ffma2(h2[j].y, w2.y, acc[j][c]);
                }
            }
        }

        // ---- horizontal add + reduce over k quarters ----
        float accs[4][6];
#pragma unroll
        for (int j = 0; j < 4; j++)
#pragma unroll
            for (int c = 0; c < 6; c++) {
                float2 p = *reinterpret_cast<float2*>(&acc[j][c]);
                float v = p.x + p.y;
                v += __shfl_xor_sync(0xffffffffu, v, 8);
                v += __shfl_xor_sync(0xffffffffu, v, 16);
                accs[j][c] = v;
            }

        float g6[6];
#pragma unroll
        for (int c = 0; c < 6; c++) {
            float v0 = (ks & 1) ? accs[1][c] : accs[0][c];
            float v2 = (ks & 1) ? accs[3][c] : accs[2][c];
            g6[c] = (ks & 2) ? v2 : v0;
        }

        // ---- gate epilogue ----
        float hv[2], cv[2];
#pragma unroll
        for (int il = 0; il < 2; il++) {
            float f = g6[il]     + bf[il]  + xf[il];
            float o = g6[2 + il] + bo[il]  + xo[il];
            float g = g6[4 + il] + bgc[il] + xg[il];
            float cn = sigm_f(f) * creg[il] + ig[il] * tanh_f(g);
            float hn = sigm_f(o) * tanh_f(cn);
            creg[il] = cn;
            hv[il] = hn; cv[il] = cn;
        }

        // ---- publish h' (critical path) -> release flag -> cold d_out stores ----
        float2 h2v = make_float2(hv[0], hv[1]);
        float2 c2v = make_float2(cv[0], cv[1]);
        __stcg(reinterpret_cast<float2*>(&g_h[(s + 1) & 1][b_glob * HH + i0]), h2v);

        __syncthreads();   // all threads' h' stores ordered before tid0's release
        if (tid == 0) {
            asm volatile("st.release.gpu.global.b32 [%0], %1;"
                         :: "l"(my_flag), "r"(s + 1) : "memory");
        }

        size_t obase = ((size_t)b_glob * SS + s) * HH + i0;
        *reinterpret_cast<float2*>(&d_out[HN_OFF + obase]) = h2v;
        *reinterpret_cast<float2*>(&d_out[CN_OFF + obase]) = c2v;
    }
}

__global__ void __launch_bounds__(256) fc_kernel(const float* __restrict__ W_fc,
                                                 const float* __restrict__ b_fc,
                                                 float* __restrict__ d_out) {
    int gidx = blockIdx.x * 8 + (threadIdx.x >> 5);
    if (gidx >= BB * SS) return;
    int lane = threadIdx.x & 31;

    const float4* h4 = reinterpret_cast<const float4*>(d_out + HN_OFF + (size_t)gidx * HH) + lane * 2;
    const float4* w4 = reinterpret_cast<const float4*>(W_fc) + lane * 2;
    float4 a = h4[0], b = h4[1];
    float4 wa = w4[0], wb = w4[1];
    float sum = a.x * wa.x + a.y * wa.y + a.z * wa.z + a.w * wa.w
              + b.x * wb.x + b.y * wb.y + b.z * wb.z + b.w * wb.w;
#pragma unroll
    for (int off = 16; off > 0; off >>= 1)
        sum += __shfl_xor_sync(0xffffffffu, sum, off);
    if (lane == 0) d_out[OUT_OFF + gidx] = sum + b_fc[0];
}

extern "C" void kernel_launch(void* const* d_in, const int* in_sizes, int n_in,
                              void* d_out, int out_size) {
    const float* x_d    = (const float*)d_in[0];
    const float* x_s    = (const float*)d_in[1];
    const float* W_ih   = (const float*)d_in[2];
    const float* W_hh   = (const float*)d_in[3];
    const float* W_sh   = (const float*)d_in[4];
    const float* bias   = (const float*)d_in[5];
    const float* bias_s = (const float*)d_in[6];
    const float* W_fc   = (const float*)d_in[7];
    const float* b_fc   = (const float*)d_in[8];
    float* out = (float*)d_out;

    const int SMEM_X    = (G3 / 2) * 64 * sizeof(float);                          // 98304
    const int SMEM_MAIN = (48 * WSTRIDE_W + 32 * WSTRIDE_H) * sizeof(float);      // 88576

    cudaFuncSetAttribute(xproj_kernel, cudaFuncAttributeMaxDynamicSharedMemorySize, SMEM_X);
    cudaFuncSetAttribute(ealstm_kernel, cudaFuncAttributeMaxDynamicSharedMemorySize, SMEM_MAIN);

    reset_kernel<<<256, 256>>>();
    xproj_kernel<<<SS, 256, SMEM_X>>>(x_d, W_ih);
    dummy_kernel<<<1, 32>>>();
    ealstm_kernel<<<128, 256, SMEM_MAIN>>>(x_s, W_hh, W_sh, bias, bias_s, out);
    fc_kernel<<<(BB * SS + 7) / 8, 256>>>(W_fc, b_fc, out);
}

// round 11
// speedup vs baseline: 1.3274x; 1.0085x over previous
#include <cuda_runtime.h>
#include <math.h>

#define BB 256
#define SS 365
#define FD 32
#define FS 27
#define HH 256
#define G3 768

#define OUT_OFF   0
#define HN_OFF    93440
#define CN_OFF    24014080

#define NCOL 96                    // 3 gates x 32 i per CTA
#define WSTRIDE_W 288              // w rows; quarter q at q*72 -> banks {0,8,16,24}
#define WSTRIDE_H 260              // h rows; 4-phase floor
#define HSM_OFF (NCOL * WSTRIDE_W)

typedef unsigned long long u64;

__device__ float g_xproj[(size_t)SS * G3 * BB];   // [s][col][b]
__device__ float g_h[2][BB * HH];                 // double-buffered hidden state
__device__ int   g_flag[128 * 32];                // flag (bt*8+ic) on its own 128B line

__device__ __forceinline__ u64 ffma2(u64 a, u64 b, u64 c) {
    u64 d;
    asm("fma.rn.f32x2 %0, %1, %2, %3;" : "=l"(d) : "l"(a), "l"(b), "l"(c));
    return d;
}
__device__ __forceinline__ u64 dup2(float x) {
    u64 r;
    asm("mov.b64 %0, {%1, %1};" : "=l"(r) : "f"(x));
    return r;
}
__device__ __forceinline__ float sigm_f(float x) {
    return __fdividef(1.0f, 1.0f + __expf(-x));
}
__device__ __forceinline__ float tanh_f(float x) {
    float t = __expf(2.0f * x);
    return 1.0f - __fdividef(2.0f, t + 1.0f);
}

__global__ void reset_kernel() {
    int idx = blockIdx.x * blockDim.x + threadIdx.x;
    if (idx < BB * HH) g_h[0][idx] = 0.0f;
    if (idx < 128 * 32) g_flag[idx] = 0;
}

__global__ void dummy_kernel() {}   // keeps ncu's captured launch on ealstm_kernel

// x_proj precompute with packed f32x2. grid: S blocks, 256 threads (thread = b).
__global__ void __launch_bounds__(256) xproj_kernel(const float* __restrict__ x_d,
                                                    const float* __restrict__ W_ih) {
    extern __shared__ float smf[];  // [pair][d*2+half], 384*64 floats
    const int s = blockIdx.x;
    const int tid = threadIdx.x;

    for (int idx = tid; idx < FD * G3; idx += 256) {
        int d = idx / G3, col = idx % G3;
        smf[(col >> 1) * 64 + d * 2 + (col & 1)] = W_ih[idx];
    }
    __syncthreads();

    u64 xp[FD];
    {
        const float4* xp4 = reinterpret_cast<const float4*>(x_d + ((size_t)tid * SS + s) * FD);
#pragma unroll
        for (int m = 0; m < 8; m++) {
            float4 v = xp4[m];
            xp[4*m]   = dup2(v.x);
            xp[4*m+1] = dup2(v.y);
            xp[4*m+2] = dup2(v.z);
            xp[4*m+3] = dup2(v.w);
        }
    }

    float* dst = g_xproj + (size_t)s * G3 * BB + tid;
    for (int p = 0; p < G3 / 2; p++) {
        u64 acc = 0ull;
        const ulonglong2* wp = reinterpret_cast<const ulonglong2*>(&smf[p * 64]);
#pragma unroll
        for (int dd = 0; dd < 16; dd++) {
            ulonglong2 q = wp[dd];
            acc = ffma2(xp[2*dd],     q.x, acc);
            acc = ffma2(xp[2*dd + 1], q.y, acc);
        }
        float2 pr = *reinterpret_cast<float2*>(&acc);
        dst[(size_t)(2*p)     * BB] = pr.x;
        dst[(size_t)(2*p + 1) * BB] = pr.y;
    }
}

// Persistent recurrence: grid 128 = 16 batch groups (16 b) x 8 CTAs (96 cols). 256 threads.
// warp w -> 4 i (w*4..w*4+3); lane: ks=lane>>3, bg=lane&7.
// Thread owns b = bt*16 + bg + 8*(ks&1), i pair = ic*32 + w*4 + 2*(ks>>1) + {0,1}.
__global__ void __launch_bounds__(256, 1) ealstm_kernel(const float* __restrict__ x_s,
                                                        const float* __restrict__ W_hh,
                                                        const float* __restrict__ W_sh,
                                                        const float* __restrict__ bias,
                                                        const float* __restrict__ bias_s,
                                                        float* __restrict__ d_out) {
    extern __shared__ float smem[];
    float* w_sm = smem;             // [96][288], k-gap swizzled
    float* h_sm = smem + HSM_OFF;   // [16][260]

    const int tid  = threadIdx.x;
    const int warp = tid >> 5;
    const int lane = tid & 31;
    const int ks   = lane >> 3;
    const int bg   = lane & 7;
    const int bt   = blockIdx.x >> 3;   // batch group (16 rows)
    const int ic   = blockIdx.x & 7;    // i-block of 32

    // ---- load W_hh slice: w_sm[c][k_phys], c = gate*32 + il, k_phys = k + (k>>6)*8 ----
    for (int idx = tid; idx < NCOL * HH; idx += 256) {
        int c = idx % NCOL, k = idx / NCOL;
        int gate = c >> 5, il = c & 31;
        int kp = k + ((k >> 6) << 3);
        w_sm[c * WSTRIDE_W + kp] = W_hh[k * G3 + gate * HH + ic * 32 + il];
    }

    const int b_glob = bt * 16 + bg + 8 * (ks & 1);
    const int i0     = ic * 32 + warp * 4 + 2 * (ks >> 1);

    float bf[2], bo[2], bgc[2], ig[2], creg[2];
#pragma unroll
    for (int il = 0; il < 2; il++) {
        int i = i0 + il;
        bf[il]  = bias[i];
        bo[il]  = bias[HH + i];
        bgc[il] = bias[2 * HH + i];
        float sum = bias_s[i];
        for (int d = 0; d < FS; d++)
            sum = fmaf(x_s[b_glob * FS + d], W_sh[d * HH + i], sum);
        ig[il] = 1.0f / (1.0f + expf(-sum));
        creg[il] = 0.0f;
    }
    __syncthreads();

    int hrow[2], wrow[12];
#pragma unroll
    for (int j = 0; j < 2; j++) hrow[j] = (bg + 8 * j) * WSTRIDE_H + ks * 64;
#pragma unroll
    for (int g = 0; g < 3; g++)
#pragma unroll
        for (int ci = 0; ci < 4; ci++)
            wrow[g * 4 + ci] = (g * 32 + warp * 4 + ci) * WSTRIDE_W + ks * 72;

    // h tile: 16 rows x 256 = 1024 float4; f = m*256 + tid, m in [0,4)
    const int hl_row = tid >> 6;          // 0..3
    const int hl_k   = (tid & 63) * 4;

    int* my_flag = &g_flag[(bt * 8 + ic) * 32];
    const int* grp_flags = &g_flag[bt * 8 * 32];

    for (int s = 0; s < SS; s++) {
        // ---- wait: every warp polls all 8 producer flags (parallel lanes) ----
        if (s > 0) {
            const int* fp = grp_flags + (lane & 7) * 32;
            for (;;) {
                int v;
                asm volatile("ld.acquire.gpu.global.b32 %0, [%1];"
                             : "=r"(v) : "l"(fp) : "memory");
                if (__all_sync(0xffffffffu, v >= s)) break;
            }
        }

        // ---- load h tile [16 x 256] from g_h double buffer ----
        {
            const float* src_base = g_h[s & 1] + (size_t)bt * 16 * HH;
#pragma unroll
            for (int m = 0; m < 4; m++) {
                int rl = 4 * m + hl_row;
                float4 v = __ldcg(reinterpret_cast<const float4*>(src_base + rl * HH + hl_k));
                *reinterpret_cast<float4*>(&h_sm[rl * WSTRIDE_H + hl_k]) = v;
            }
        }

        // ---- prefetch x_proj additive terms ----
        float xf[2], xo[2], xg[2];
        {
            const size_t xrow = (size_t)s * G3 * BB + b_glob;
#pragma unroll
            for (int il = 0; il < 2; il++) {
                int i = i0 + il;
                xf[il] = __ldg(&g_xproj[xrow + (size_t)i * BB]);
                xo[il] = __ldg(&g_xproj[xrow + (size_t)(HH + i) * BB]);
                xg[il] = __ldg(&g_xproj[xrow + (size_t)(2 * HH + i) * BB]);
            }
        }
        __syncthreads();

        // ---- packed f32x2 accumulation: 2 rows x 12 cols x this lane's k quarter ----
        u64 acc[2][12];
#pragma unroll
        for (int j = 0; j < 2; j++)
#pragma unroll
            for (int c = 0; c < 12; c++) acc[j][c] = 0ull;

#pragma unroll 4
        for (int kk = 0; kk < 16; kk++) {
            const int o = kk * 4;
            ulonglong2 h2[2];
#pragma unroll
            for (int j = 0; j < 2; j++)
                h2[j] = *reinterpret_cast<const ulonglong2*>(&h_sm[hrow[j] + o]);
#pragma unroll
            for (int c = 0; c < 12; c++) {
                ulonglong2 w2 = *reinterpret_cast<const ulonglong2*>(&w_sm[wrow[c] + o]);
#pragma unroll
                for (int j = 0; j < 2; j++) {
                    acc[j][c] = ffma2(h2[j].x, w2.x, acc[j][c]);
                    acc[j][c] = ffma2(h2[j].y, w2.y, acc[j][c]);
                }
            }
        }

        // ---- horizontal add + reduce over k quarters ----
        float accs[2][12];
#pragma unroll
        for (int j = 0; j < 2; j++)
#pragma unroll
            for (int c = 0; c < 12; c++) {
                float2 p = *reinterpret_cast<float2*>(&acc[j][c]);
                float v = p.x + p.y;
                v += __shfl_xor_sync(0xffffffffu, v, 8);
                v += __shfl_xor_sync(0xffffffffu, v, 16);
                accs[j][c] = v;
            }

        // ---- select this thread's 6 gate values (b via ks&1, i-pair via ks&2) ----
        float g6[6];
#pragma unroll
        for (int g = 0; g < 3; g++)
#pragma unroll
            for (int il = 0; il < 2; il++) {
                float va = (ks & 2) ? accs[0][g*4 + 2 + il] : accs[0][g*4 + il];
                float vb = (ks & 2) ? accs[1][g*4 + 2 + il] : accs[1][g*4 + il];
                g6[g * 2 + il] = (ks & 1) ? vb : va;
            }

        // ---- gate epilogue ----
        float hv[2], cv[2];
#pragma unroll
        for (int il = 0; il < 2; il++) {
            float f = g6[il]     + bf[il]  + xf[il];
            float o = g6[2 + il] + bo[il]  + xo[il];
            float g = g6[4 + il] + bgc[il] + xg[il];
            float cn = sigm_f(f) * creg[il] + ig[il] * tanh_f(g);
            float hn = sigm_f(o) * tanh_f(cn);
            creg[il] = cn;
            hv[il] = hn; cv[il] = cn;
        }

        // ---- publish h' (critical path) -> release flag -> cold d_out stores ----
        float2 h2v = make_float2(hv[0], hv[1]);
        float2 c2v = make_float2(cv[0], cv[1]);
        __stcg(reinterpret_cast<float2*>(&g_h[(s + 1) & 1][b_glob * HH + i0]), h2v);

        __syncthreads();   // all threads' h' stores ordered before tid0's release
        if (tid == 0) {
            asm volatile("st.release.gpu.global.b32 [%0], %1;"
                         :: "l"(my_flag), "r"(s + 1) : "memory");
        }

        size_t obase = ((size_t)b_glob * SS + s) * HH + i0;
        *reinterpret_cast<float2*>(&d_out[HN_OFF + obase]) = h2v;
        *reinterpret_cast<float2*>(&d_out[CN_OFF + obase]) = c2v;
    }
}

__global__ void __launch_bounds__(256) fc_kernel(const float* __restrict__ W_fc,
                                                 const float* __restrict__ b_fc,
                                                 float* __restrict__ d_out) {
    int gidx = blockIdx.x * 8 + (threadIdx.x >> 5);
    if (gidx >= BB * SS) return;
    int lane = threadIdx.x & 31;

    const float4* h4 = reinterpret_cast<const float4*>(d_out + HN_OFF + (size_t)gidx * HH) + lane * 2;
    const float4* w4 = reinterpret_cast<const float4*>(W_fc) + lane * 2;
    float4 a = h4[0], b = h4[1];
    float4 wa = w4[0], wb = w4[1];
    float sum = a.x * wa.x + a.y * wa.y + a.z * wa.z + a.w * wa.w
              + b.x * wb.x + b.y * wb.y + b.z * wb.z + b.w * wb.w;
#pragma unroll
    for (int off = 16; off > 0; off >>= 1)
        sum += __shfl_xor_sync(0xffffffffu, sum, off);
    if (lane == 0) d_out[OUT_OFF + gidx] = sum + b_fc[0];
}

extern "C" void kernel_launch(void* const* d_in, const int* in_sizes, int n_in,
                              void* d_out, int out_size) {
    const float* x_d    = (const float*)d_in[0];
    const float* x_s    = (const float*)d_in[1];
    const float* W_ih   = (const float*)d_in[2];
    const float* W_hh   = (const float*)d_in[3];
    const float* W_sh   = (const float*)d_in[4];
    const float* bias   = (const float*)d_in[5];
    const float* bias_s = (const float*)d_in[6];
    const float* W_fc   = (const float*)d_in[7];
    const float* b_fc   = (const float*)d_in[8];
    float* out = (float*)d_out;

    const int SMEM_X    = (G3 / 2) * 64 * sizeof(float);                          // 98304
    const int SMEM_MAIN = (NCOL * WSTRIDE_W + 16 * WSTRIDE_H) * sizeof(float);    // 127232

    cudaFuncSetAttribute(xproj_kernel, cudaFuncAttributeMaxDynamicSharedMemorySize, SMEM_X);
    cudaFuncSetAttribute(ealstm_kernel, cudaFuncAttributeMaxDynamicSharedMemorySize, SMEM_MAIN);

    reset_kernel<<<256, 256>>>();
    xproj_kernel<<<SS, 256, SMEM_X>>>(x_d, W_ih);
    dummy_kernel<<<1, 32>>>();
    ealstm_kernel<<<128, 256, SMEM_MAIN>>>(x_s, W_hh, W_sh, bias, bias_s, out);
    fc_kernel<<<(BB * SS + 7) / 8, 256>>>(W_fc, b_fc, out);
}